// round 15
// baseline (speedup 1.0000x reference)
#include <cuda_runtime.h>
#include <cuda_fp16.h>
#include <math.h>
#include <stdint.h>

#define HW 65536
#define PLANE 16777216ULL   /* 8 * 65536 * 32 halves = one direction plane */

// ---------------------------------------------------------------------------
// Scratch (no allocations allowed)
// ---------------------------------------------------------------------------
__device__ __half g_c16[8ULL * 65536 * 32];    //  32 MB NHWC fp16 conv outputs
__device__ __half g_a16[4ULL * 8 * 65536 * 32];// 128 MB direction-major irnn outputs
__device__ __align__(16) char g_wb[167424];    // prepped B fp16 (padded row-major)
// conv1: @0 (18944, BSTR=592) ; conv2: @18944 (74240, BSTR=2320) ; conv3: @93184

// ---------------------------------------------------------------------------
__device__ __forceinline__ uint32_t smem_u32(const void* p) {
    uint32_t a;
    asm("{ .reg .u64 t; cvta.to.shared.u64 t, %1; cvt.u32.u64 %0, t; }" : "=r"(a) : "l"(p));
    return a;
}
__device__ __forceinline__ void ldm4(uint32_t* r, uint32_t a) {
    asm volatile("ldmatrix.sync.aligned.m8n8.x4.shared.b16 {%0,%1,%2,%3}, [%4];"
                 : "=r"(r[0]), "=r"(r[1]), "=r"(r[2]), "=r"(r[3]) : "r"(a));
}
__device__ __forceinline__ void mma16816(float* c, const uint32_t* a, uint32_t b0, uint32_t b1) {
    asm volatile("mma.sync.aligned.m16n8k16.row.col.f32.f16.f16.f32 "
        "{%0,%1,%2,%3}, {%4,%5,%6,%7}, {%8,%9}, {%0,%1,%2,%3};"
        : "+f"(c[0]), "+f"(c[1]), "+f"(c[2]), "+f"(c[3])
        : "r"(a[0]), "r"(a[1]), "r"(a[2]), "r"(a[3]), "r"(b0), "r"(b1));
}
__device__ __forceinline__ void cp16(uint32_t saddr, const void* gaddr, int sz) {
    asm volatile("cp.async.cg.shared.global [%0], [%1], 16, %2;"
                 :: "r"(saddr), "l"(gaddr), "r"(sz));
}
__device__ __forceinline__ void cp_commit() { asm volatile("cp.async.commit_group;"); }
__device__ __forceinline__ void cp_wait0()  { asm volatile("cp.async.wait_group 0;"); }
__device__ __forceinline__ void cp_wait1()  { asm volatile("cp.async.wait_group 1;"); }

// ---------------------------------------------------------------------------
// Weight prep (all three in one launch; blockIdx.y selects the conv).
// K order: k = dy*3*CIN + dx*CIN + c.
// ---------------------------------------------------------------------------
__global__ void prep_all(const float* __restrict__ w1, const float* __restrict__ w2,
                         const float* __restrict__ w3, char* __restrict__ out)
{
    const int which = blockIdx.y;
    const float* w = (which == 0) ? w1 : (which == 1) ? w2 : w3;
    const int CIN  = (which == 0) ? 32 : 128;
    char* bimg = out + ((which == 0) ? 0 : (which == 1) ? 18944 : 93184);

    int K = 9 * CIN, KP = K + 8, BSTR = K * 2 + 16;
    int idx = blockIdx.x * 256 + threadIdx.x;
    if (idx >= 32 * KP) return;
    int n = idx / KP, k = idx - n * KP;
    float v = 0.f;
    if (k < K) {
        int dyi = k / (3 * CIN);
        int r   = k - dyi * 3 * CIN;
        int dxi = r / CIN;
        int c   = r - dxi * CIN;
        v = w[(n * CIN + c) * 9 + dyi * 3 + dxi];
    }
    *(__half*)(bimg + n * BSTR + k * 2) = __float2half(v);
}

// ---------------------------------------------------------------------------
// conv1: HMMA implicit-GEMM 3x3, CIN=32, reads NCHW fp32 x DIRECTLY.
// A staged per input row: px-coalesced fp32 LDG into regs (double-buffered),
// fp16 convert at STS.  B fp16 in smem.  Output fp16 NHWC (32 ch).
// smem: [B 18944][A0 10400][A1 10400]
// ---------------------------------------------------------------------------
__global__ __launch_bounds__(256, 1)
void conv1_mma(const float* __restrict__ x, const char* __restrict__ wb,
               __half* __restrict__ out)
{
    constexpr int CIN  = 32;
    constexpr int ASTR = 80;       // 32*2 + 16
    constexpr int BSTR = 592;      // 288*2 + 16
    constexpr int BBYT = 18944;
    constexpr int ABYT = 130 * ASTR;
    constexpr int NE   = 130 * 32; // 4160 staged halves per row
    constexpr int NI   = 17;       // ceil(4160/256)

    extern __shared__ __align__(16) char smem[];
    const int tid  = threadIdx.x;
    const int lane = tid & 31;
    const int wid  = tid >> 5;
    const int w0   = blockIdx.x << 7;
    const int h0   = blockIdx.y << 2;
    const int b    = blockIdx.z;

    const uint32_t s0  = smem_u32(smem);
    const uint32_t sB  = s0;
    const uint32_t sA0 = s0 + BBYT;

    // B copy (cp.async group 0)
    {
        for (int i = tid; i < BBYT / 16; i += 256)
            cp16(sB + i * 16, wb + i * 16, 16);
        cp_commit();
    }

    float rv[NI];
    auto load_regs = [&](int s) {
        const int ir = h0 - 1 + s;
        if ((unsigned)ir < 256u) {
#pragma unroll
            for (int i = 0; i < NI; i++) {
                int idx = tid + i * 256;
                float v = 0.f;
                if (idx < NE) {
                    int c = idx / 130, px = idx - c * 130;
                    int w = w0 - 1 + px;
                    if ((unsigned)w < 256u)
                        v = x[((size_t)(b * 32 + c) << 16) + ir * 256 + w];
                }
                rv[i] = v;
            }
        } else {
#pragma unroll
            for (int i = 0; i < NI; i++) rv[i] = 0.f;
        }
    };
    load_regs(0);

    const int m0 = wid * 16;
    const uint32_t aRowOff = (uint32_t)(lane & 15) * ASTR + ((lane & 16) ? 16u : 0u);
    const uint32_t bLM = (uint32_t)((lane & 7) + ((lane & 16) ? 8 : 0)) * BSTR
                       + (uint32_t)((lane >> 3) & 1) * 16;

    float acc[4][16];
#pragma unroll
    for (int r = 0; r < 4; r++)
#pragma unroll
        for (int i = 0; i < 16; i++) acc[r][i] = 0.f;

    for (int s = 0; s < 6; s++) {
        const int ir = h0 - 1 + s;
        const uint32_t sA = sA0 + (uint32_t)(s & 1) * ABYT;
        __syncthreads();                    // buf (s&1) free of readers
        // STS current row from regs
#pragma unroll
        for (int i = 0; i < NI; i++) {
            int idx = tid + i * 256;
            if (idx < NE) {
                int c = idx / 130, px = idx - c * 130;
                *(__half*)(smem + (sA - s0) + px * ASTR + c * 2) = __float2half(rv[i]);
            }
        }
        if (s < 5) load_regs(s + 1);        // LDG next row (overlaps compute)
        if (s == 0) cp_wait0();             // B arrived
        __syncthreads();
        if ((unsigned)ir >= 256u) continue;

#pragma unroll
        for (int dx = 0; dx < 3; dx++) {
#pragma unroll
            for (int kc = 0; kc < 2; kc++) {
                uint32_t a[4];
                ldm4(a, sA + (uint32_t)(m0 + dx) * ASTR + kc * 32 + aRowOff);
#pragma unroll
                for (int r = 0; r < 4; r++) {
                    const int dy = s - r;
                    if (dy < 0 || dy > 2) continue;
                    const uint32_t kb = (uint32_t)(dy * 96 + dx * 32 + kc * 16) * 2;
                    uint32_t bh[4], bh2[4];
                    ldm4(bh,  sB + bLM + kb);
                    ldm4(bh2, sB + bLM + kb + 16 * BSTR);
                    float* a0 = acc[r];
                    mma16816(a0 + 0,  a, bh[0],  bh[1]);
                    mma16816(a0 + 4,  a, bh[2],  bh[3]);
                    mma16816(a0 + 8,  a, bh2[0], bh2[1]);
                    mma16816(a0 + 12, a, bh2[2], bh2[3]);
                }
            }
        }
    }

    const int prow = m0 + (lane >> 2);
#pragma unroll
    for (int r = 0; r < 4; r++) {
        const int h = h0 + r;
        __half* ob = out + ((size_t)b * HW + (size_t)h * 256 + w0) * 32;
#pragma unroll
        for (int nt = 0; nt < 4; nt++) {
            int ch = nt * 8 + (lane & 3) * 2;
            *(__half2*)(ob + (size_t)prow * 32 + ch) =
                __floats2half2_rn(acc[r][nt * 4 + 0], acc[r][nt * 4 + 1]);
            *(__half2*)(ob + (size_t)(prow + 8) * 32 + ch) =
                __floats2half2_rn(acc[r][nt * 4 + 2], acc[r][nt * 4 + 3]);
        }
    }
}

// ---------------------------------------------------------------------------
// conv2/conv3: HMMA implicit-GEMM 3x3, CIN=128 (four direction planes),
// 4 output rows/CTA, 8 warps, cp.async double-buffered A.
// FUSE folds relu + 1x1 conv + sigmoid.
// smem: [B BBYT][A buf0 ABYT][A buf1 ABYT]
// ---------------------------------------------------------------------------
template<bool FUSE>
__global__ __launch_bounds__(256, 1)
void conv_mma(const __half* __restrict__ a16, const char* __restrict__ wb,
              const float* __restrict__ wout, void* __restrict__ outv)
{
    constexpr int CIN   = 128;
    constexpr int K     = 9 * CIN;
    constexpr int ASTR  = CIN * 2 + 16;
    constexpr int BSTR  = K * 2 + 16;
    constexpr int BBYT  = 32 * BSTR;
    constexpr int V4    = CIN / 8;
    constexpr int ABYT  = 130 * ASTR;

    extern __shared__ __align__(16) char smem[];
    const int tid  = threadIdx.x;
    const int lane = tid & 31;
    const int wid  = tid >> 5;
    const int w0   = blockIdx.x << 7;
    const int h0   = blockIdx.y << 2;
    const int b    = blockIdx.z;

    const uint32_t s0  = smem_u32(smem);
    const uint32_t sB  = s0;
    const uint32_t sA0 = s0 + BBYT;

    // group 0: B copy
    {
        for (int i = tid; i < BBYT / 16; i += 256)
            cp16(sB + i * 16, wb + i * 16, 16);
        cp_commit();
    }

    auto prefetch = [&](int s) {
        const int ir = h0 - 1 + s;
        const uint32_t abase = sA0 + (uint32_t)(s & 1) * ABYT;
        if ((unsigned)ir < 256u) {
            const size_t rowbase = ((size_t)b * HW + (size_t)ir * 256);
            for (int i = tid; i < 130 * V4; i += 256) {
                int px = i / V4, v = i - px * V4;
                int w  = w0 - 1 + px;
                int ok = ((unsigned)w < 256u);
                int wc = ok ? w : 0;
                int plane = v >> 2;
                const __half* src = a16 + (size_t)plane * PLANE + (rowbase + wc) * 32 + (v & 3) * 8;
                cp16(abase + (uint32_t)(px * ASTR + v * 16), src, ok ? 16 : 0);
            }
        }
        cp_commit();
    };
    prefetch(0);

    const int m0 = wid * 16;
    const uint32_t aRowOff = (uint32_t)(lane & 15) * ASTR + ((lane & 16) ? 16u : 0u);
    const uint32_t bLM = (uint32_t)((lane & 7) + ((lane & 16) ? 8 : 0)) * BSTR
                       + (uint32_t)((lane >> 3) & 1) * 16;

    float acc[4][16];
#pragma unroll
    for (int r = 0; r < 4; r++)
#pragma unroll
        for (int i = 0; i < 16; i++) acc[r][i] = 0.f;

    for (int s = 0; s < 6; s++) {
        const int ir = h0 - 1 + s;
        __syncthreads();
        if (s < 5) prefetch(s + 1);
        if (s < 5) cp_wait1(); else cp_wait0();
        __syncthreads();
        if ((unsigned)ir >= 256u) continue;

        const uint32_t sA = sA0 + (uint32_t)(s & 1) * ABYT;

#pragma unroll
        for (int dx = 0; dx < 3; dx++) {
#pragma unroll
            for (int kc = 0; kc < CIN / 16; kc++) {
                uint32_t a[4];
                ldm4(a, sA + (uint32_t)(m0 + dx) * ASTR + kc * 32 + aRowOff);
#pragma unroll
                for (int r = 0; r < 4; r++) {
                    const int dy = s - r;
                    if (dy < 0 || dy > 2) continue;
                    const uint32_t kb = (uint32_t)(dy * 3 * CIN + dx * CIN + kc * 16) * 2;
                    uint32_t bh[4], bh2[4];
                    ldm4(bh,  sB + bLM + kb);
                    ldm4(bh2, sB + bLM + kb + 16 * BSTR);
                    float* a0 = acc[r];
                    mma16816(a0 + 0,  a, bh[0],  bh[1]);
                    mma16816(a0 + 4,  a, bh[2],  bh[3]);
                    mma16816(a0 + 8,  a, bh2[0], bh2[1]);
                    mma16816(a0 + 12, a, bh2[2], bh2[3]);
                }
            }
        }
    }

    const int prow = m0 + (lane >> 2);
#pragma unroll
    for (int r = 0; r < 4; r++) {
        const int h = h0 + r;
        if (!FUSE) {
            __half* ob = (__half*)outv + ((size_t)b * HW + (size_t)h * 256 + w0) * 32;
#pragma unroll
            for (int nt = 0; nt < 4; nt++) {
                int ch = nt * 8 + (lane & 3) * 2;
                *(__half2*)(ob + (size_t)prow * 32 + ch) =
                    __floats2half2_rn(acc[r][nt * 4 + 0], acc[r][nt * 4 + 1]);
                *(__half2*)(ob + (size_t)(prow + 8) * 32 + ch) =
                    __floats2half2_rn(acc[r][nt * 4 + 2], acc[r][nt * 4 + 3]);
            }
        } else {
            float s0v = 0.f, s1v = 0.f;
#pragma unroll
            for (int nt = 0; nt < 4; nt++) {
                int ch = nt * 8 + (lane & 3) * 2;
                float wa = __ldg(&wout[ch]), wb2 = __ldg(&wout[ch + 1]);
                s0v += fmaxf(acc[r][nt * 4 + 0], 0.f) * wa + fmaxf(acc[r][nt * 4 + 1], 0.f) * wb2;
                s1v += fmaxf(acc[r][nt * 4 + 2], 0.f) * wa + fmaxf(acc[r][nt * 4 + 3], 0.f) * wb2;
            }
            s0v += __shfl_xor_sync(0xffffffffu, s0v, 1);
            s0v += __shfl_xor_sync(0xffffffffu, s0v, 2);
            s1v += __shfl_xor_sync(0xffffffffu, s1v, 1);
            s1v += __shfl_xor_sync(0xffffffffu, s1v, 2);
            if ((lane & 3) == 0) {
                float* outp = (float*)outv;
                size_t ob = (size_t)b * HW + (size_t)h * 256 + w0;
                outp[ob + prow]     = 1.0f / (1.0f + expf(-s0v));
                outp[ob + prow + 8] = 1.0f / (1.0f + expf(-s1v));
            }
        }
    }
}

// ---------------------------------------------------------------------------
// IRNN: all 4 directional scans in ONE kernel (blockIdx.y = direction).
// Thread owns a channel pair; output: direction-major plane [B][HW][32].
// ---------------------------------------------------------------------------
template<bool REV>
__device__ __forceinline__
void scan_h_body(const __half* __restrict__ in, __half* __restrict__ plane,
                 float wc0, float bc0, float wc1, float bc1, int c)
{
    int t = blockIdx.x * 256 + threadIdx.x;      // over B*W*16 = 32768
    int w = (t >> 4) & 255, b = t >> 12;
    const __half2* ip = (const __half2*)(in + (size_t)b * HW * 32 + (size_t)w * 32 + c);
    __half2* op = (__half2*)(plane + ((size_t)b * HW + w) * 32 + c);

    __half2 v0 = REV ? ip[(size_t)255 * 4096] : ip[0];
    float h0 = __low2float(v0), h1 = __high2float(v0);
    op[(size_t)(REV ? 255 : 0) * 4096] = v0;
#pragma unroll 8
    for (int i = 1; i < 256; i++) {
        int y = REV ? (255 - i) : i;
        __half2 v = ip[(size_t)y * 4096];
        h0 = fmaxf(wc0 * h0 + (bc0 + __low2float(v)),  0.f);
        h1 = fmaxf(wc1 * h1 + (bc1 + __high2float(v)), 0.f);
        op[(size_t)y * 4096] = __floats2half2_rn(h0, h1);
    }
}

template<bool REV>
__device__ __forceinline__
void scan_w_body(const __half* __restrict__ in, __half* __restrict__ plane,
                 float wc0, float bc0, float wc1, float bc1, int c)
{
    int t = blockIdx.x * 256 + threadIdx.x;      // over B*H*16 = 32768
    int h = (t >> 4) & 255, b = t >> 12;
    const __half2* ip = (const __half2*)(in + (size_t)b * HW * 32 + (size_t)h * 8192 + c);
    __half2* op = (__half2*)(plane + ((size_t)b * HW + (size_t)h * 256) * 32 + c);

    __half2 v0 = REV ? ip[255 * 16] : ip[0];
    float h0 = __low2float(v0), h1 = __high2float(v0);
    op[(size_t)(REV ? 255 : 0) * 16] = v0;
#pragma unroll 8
    for (int i = 1; i < 256; i++) {
        int w = REV ? (255 - i) : i;
        __half2 v = ip[w * 16];
        h0 = fmaxf(wc0 * h0 + (bc0 + __low2float(v)),  0.f);
        h1 = fmaxf(wc1 * h1 + (bc1 + __high2float(v)), 0.f);
        op[(size_t)w * 16] = __floats2half2_rn(h0, h1);
    }
}

__global__ __launch_bounds__(256)
void scan_all(const __half* __restrict__ in, __half* __restrict__ o16,
              const float* __restrict__ ws, const float* __restrict__ bs)
{
    const int d = blockIdx.y;
    const int c = (threadIdx.x & 15) * 2;
    const float wc0 = ws[d * 32 + c],     bc0 = bs[d * 32 + c];
    const float wc1 = ws[d * 32 + c + 1], bc1 = bs[d * 32 + c + 1];
    __half* plane = o16 + (size_t)d * PLANE;
    if      (d == 0) scan_h_body<true >(in, plane, wc0, bc0, wc1, bc1, c);   // up
    else if (d == 1) scan_w_body<false>(in, plane, wc0, bc0, wc1, bc1, c);   // right
    else if (d == 2) scan_h_body<false>(in, plane, wc0, bc0, wc1, bc1, c);   // down
    else             scan_w_body<true >(in, plane, wc0, bc0, wc1, bc1, c);   // left
}

// ---------------------------------------------------------------------------
extern "C" void kernel_launch(void* const* d_in, const int* in_sizes, int n_in,
                              void* d_out, int out_size)
{
    const float* x   = (const float*)d_in[0];
    const float* w1  = (const float*)d_in[1];
    const float* w2  = (const float*)d_in[2];
    const float* w3  = (const float*)d_in[3];
    const float* wo  = (const float*)d_in[4];
    const float* i1w = (const float*)d_in[5];
    const float* i1b = (const float*)d_in[6];
    const float* i2w = (const float*)d_in[7];
    const float* i2b = (const float*)d_in[8];
    float* outp = (float*)d_out;

    __half *gc, *ga;  char* gwb;
    cudaGetSymbolAddress((void**)&gc,  g_c16);
    cudaGetSymbolAddress((void**)&ga,  g_a16);
    cudaGetSymbolAddress((void**)&gwb, g_wb);

    // smem: conv1 = 18944 + 2*10400 = 39744 ; conv2/3 = 74240 + 2*35360 = 144960
    cudaFuncSetAttribute(conv1_mma,       cudaFuncAttributeMaxDynamicSharedMemorySize, 39744);
    cudaFuncSetAttribute(conv_mma<false>, cudaFuncAttributeMaxDynamicSharedMemorySize, 144960);
    cudaFuncSetAttribute(conv_mma<true >, cudaFuncAttributeMaxDynamicSharedMemorySize, 144960);

    // all weight prep in one launch (w2/w3 need 145 blocks; w1 guarded)
    prep_all<<<dim3(145, 3), 256>>>(w1, w2, w3, gwb);

    dim3 cg(2, 64, 8);   // 4 output rows per CTA
    conv1_mma<<<cg, 256, 39744>>>(x, gwb + 0, gc);

    scan_all<<<dim3(128, 4), 256>>>(gc, ga, i1w, i1b);

    conv_mma<false><<<cg, 256, 144960>>>(ga, gwb + 18944, nullptr, gc);

    scan_all<<<dim3(128, 4), 256>>>(gc, ga, i2w, i2b);

    conv_mma<true><<<cg, 256, 144960>>>(ga, gwb + 93184, wo, outp);
}

// round 16
// speedup vs baseline: 1.1763x; 1.1763x over previous
#include <cuda_runtime.h>
#include <cuda_fp16.h>
#include <math.h>
#include <stdint.h>

#define HW 65536
#define PLANE 16777216ULL   /* 8 * 65536 * 32 halves = one direction plane */

// ---------------------------------------------------------------------------
// Scratch (no allocations allowed)
// ---------------------------------------------------------------------------
__device__ __half g_c16[8ULL * 65536 * 32];    //  32 MB NHWC fp16 conv outputs
__device__ __half g_x16[8ULL * 65536 * 32];    //  32 MB NHWC fp16 x
__device__ __half g_a16[4ULL * 8 * 65536 * 32];// 128 MB direction-major irnn outputs
__device__ __align__(16) char g_wb[167424];    // prepped B fp16 (padded row-major)
// conv1: @0 (18944, BSTR=592) ; conv2: @18944 (74240, BSTR=2320) ; conv3: @93184

// ---------------------------------------------------------------------------
__device__ __forceinline__ uint32_t smem_u32(const void* p) {
    uint32_t a;
    asm("{ .reg .u64 t; cvta.to.shared.u64 t, %1; cvt.u32.u64 %0, t; }" : "=r"(a) : "l"(p));
    return a;
}
__device__ __forceinline__ void ldm4(uint32_t* r, uint32_t a) {
    asm volatile("ldmatrix.sync.aligned.m8n8.x4.shared.b16 {%0,%1,%2,%3}, [%4];"
                 : "=r"(r[0]), "=r"(r[1]), "=r"(r[2]), "=r"(r[3]) : "r"(a));
}
__device__ __forceinline__ void mma16816(float* c, const uint32_t* a, uint32_t b0, uint32_t b1) {
    asm volatile("mma.sync.aligned.m16n8k16.row.col.f32.f16.f16.f32 "
        "{%0,%1,%2,%3}, {%4,%5,%6,%7}, {%8,%9}, {%0,%1,%2,%3};"
        : "+f"(c[0]), "+f"(c[1]), "+f"(c[2]), "+f"(c[3])
        : "r"(a[0]), "r"(a[1]), "r"(a[2]), "r"(a[3]), "r"(b0), "r"(b1));
}
__device__ __forceinline__ void cp16(uint32_t saddr, const void* gaddr, int sz) {
    asm volatile("cp.async.cg.shared.global [%0], [%1], 16, %2;"
                 :: "r"(saddr), "l"(gaddr), "r"(sz));
}
__device__ __forceinline__ void cp_commit() { asm volatile("cp.async.commit_group;"); }
__device__ __forceinline__ void cp_wait0()  { asm volatile("cp.async.wait_group 0;"); }
__device__ __forceinline__ void cp_wait1()  { asm volatile("cp.async.wait_group 1;"); }

// ---------------------------------------------------------------------------
// Weight prep (all three in one launch; blockIdx.y selects the conv).
// ---------------------------------------------------------------------------
__global__ void prep_all(const float* __restrict__ w1, const float* __restrict__ w2,
                         const float* __restrict__ w3, char* __restrict__ out)
{
    const int which = blockIdx.y;
    const float* w = (which == 0) ? w1 : (which == 1) ? w2 : w3;
    const int CIN  = (which == 0) ? 32 : 128;
    char* bimg = out + ((which == 0) ? 0 : (which == 1) ? 18944 : 93184);

    int K = 9 * CIN, KP = K + 8, BSTR = K * 2 + 16;
    int idx = blockIdx.x * 256 + threadIdx.x;
    if (idx >= 32 * KP) return;
    int n = idx / KP, k = idx - n * KP;
    float v = 0.f;
    if (k < K) {
        int dyi = k / (3 * CIN);
        int r   = k - dyi * 3 * CIN;
        int dxi = r / CIN;
        int c   = r - dxi * CIN;
        v = w[(n * CIN + c) * 9 + dyi * 3 + dxi];
    }
    *(__half*)(bimg + n * BSTR + k * 2) = __float2half(v);
}

// ---------------------------------------------------------------------------
// x (NCHW fp32) -> NHWC fp16 (32 ch)
// ---------------------------------------------------------------------------
__global__ __launch_bounds__(256)
void transpose_x(const float* __restrict__ x, __half* __restrict__ o16)
{
    __shared__ float t[32][33];
    int b = blockIdx.y;
    int p0 = blockIdx.x * 32;
    int lane = threadIdx.x & 31, grp = threadIdx.x >> 5;
#pragma unroll
    for (int i = 0; i < 4; i++) {
        int c = grp + i * 8;
        t[c][lane] = x[((size_t)b * 32 + c) * HW + p0 + lane];
    }
    __syncthreads();
#pragma unroll
    for (int i = 0; i < 4; i++) {
        int p = grp + i * 8;
        o16[((size_t)b * HW + p0 + p) * 32 + lane] = __float2half(t[lane][p]);
    }
}

// ---------------------------------------------------------------------------
// conv1: CIN=32, 128px x 4 rows per CTA (R14 structure).
// ---------------------------------------------------------------------------
__global__ __launch_bounds__(256, 1)
void conv1_mma(const __half* __restrict__ a16, const char* __restrict__ wb,
               __half* __restrict__ out)
{
    constexpr int CIN  = 32;
    constexpr int ASTR = 80;
    constexpr int BSTR = 592;
    constexpr int BBYT = 18944;
    constexpr int V4   = 4;
    constexpr int ABYT = 130 * ASTR;

    extern __shared__ __align__(16) char smem[];
    const int tid  = threadIdx.x;
    const int lane = tid & 31;
    const int wid  = tid >> 5;
    const int w0   = blockIdx.x << 7;
    const int h0   = blockIdx.y << 2;
    const int b    = blockIdx.z;

    const uint32_t s0  = smem_u32(smem);
    const uint32_t sB  = s0;
    const uint32_t sA0 = s0 + BBYT;

    {
        for (int i = tid; i < BBYT / 16; i += 256)
            cp16(sB + i * 16, wb + i * 16, 16);
        cp_commit();
    }

    auto prefetch = [&](int s) {
        const int ir = h0 - 1 + s;
        const uint32_t abase = sA0 + (uint32_t)(s & 1) * ABYT;
        if ((unsigned)ir < 256u) {
            const size_t rowbase = ((size_t)b * HW + (size_t)ir * 256);
            for (int i = tid; i < 130 * V4; i += 256) {
                int px = i / V4, v = i - px * V4;
                int w  = w0 - 1 + px;
                int ok = ((unsigned)w < 256u);
                int wc = ok ? w : 0;
                cp16(abase + (uint32_t)(px * ASTR + v * 16),
                     a16 + (rowbase + wc) * 32 + v * 8, ok ? 16 : 0);
            }
        }
        cp_commit();
    };
    prefetch(0);

    const int m0 = wid * 16;
    const uint32_t aRowOff = (uint32_t)(lane & 15) * ASTR + ((lane & 16) ? 16u : 0u);
    const uint32_t bLM = (uint32_t)((lane & 7) + ((lane & 16) ? 8 : 0)) * BSTR
                       + (uint32_t)((lane >> 3) & 1) * 16;

    float acc[4][16];
#pragma unroll
    for (int r = 0; r < 4; r++)
#pragma unroll
        for (int i = 0; i < 16; i++) acc[r][i] = 0.f;

    for (int s = 0; s < 6; s++) {
        const int ir = h0 - 1 + s;
        __syncthreads();
        if (s < 5) prefetch(s + 1);
        if (s < 5) cp_wait1(); else cp_wait0();
        __syncthreads();
        if ((unsigned)ir >= 256u) continue;

        const uint32_t sA = sA0 + (uint32_t)(s & 1) * ABYT;
#pragma unroll
        for (int dx = 0; dx < 3; dx++) {
#pragma unroll
            for (int kc = 0; kc < 2; kc++) {
                uint32_t a[4];
                ldm4(a, sA + (uint32_t)(m0 + dx) * ASTR + kc * 32 + aRowOff);
#pragma unroll
                for (int r = 0; r < 4; r++) {
                    const int dy = s - r;
                    if (dy < 0 || dy > 2) continue;
                    const uint32_t kb = (uint32_t)(dy * 96 + dx * 32 + kc * 16) * 2;
                    uint32_t bh[4], bh2[4];
                    ldm4(bh,  sB + bLM + kb);
                    ldm4(bh2, sB + bLM + kb + 16 * BSTR);
                    float* a0 = acc[r];
                    mma16816(a0 + 0,  a, bh[0],  bh[1]);
                    mma16816(a0 + 4,  a, bh[2],  bh[3]);
                    mma16816(a0 + 8,  a, bh2[0], bh2[1]);
                    mma16816(a0 + 12, a, bh2[2], bh2[3]);
                }
            }
        }
    }

    const int prow = m0 + (lane >> 2);
#pragma unroll
    for (int r = 0; r < 4; r++) {
        const int h = h0 + r;
        __half* ob = out + ((size_t)b * HW + (size_t)h * 256 + w0) * 32;
#pragma unroll
        for (int nt = 0; nt < 4; nt++) {
            int ch = nt * 8 + (lane & 3) * 2;
            *(__half2*)(ob + (size_t)prow * 32 + ch) =
                __floats2half2_rn(acc[r][nt * 4 + 0], acc[r][nt * 4 + 1]);
            *(__half2*)(ob + (size_t)(prow + 8) * 32 + ch) =
                __floats2half2_rn(acc[r][nt * 4 + 2], acc[r][nt * 4 + 3]);
        }
    }
}

// ---------------------------------------------------------------------------
// conv2/conv3: CIN=128, 256px-wide CTA x 2 output rows, 8 warps, each m32
// (two m16 tiles sharing the same B fragments -> B-ldm per MMA halves).
// cp.async double-buffered A (4 stages).  FUSE folds relu+1x1+sigmoid.
// smem: [B 74240][A0 70176][A1 70176] = 214592
// ---------------------------------------------------------------------------
template<bool FUSE>
__global__ __launch_bounds__(256, 1)
void conv_wide(const __half* __restrict__ a16, const char* __restrict__ wb,
               const float* __restrict__ wout, void* __restrict__ outv)
{
    constexpr int CIN   = 128;
    constexpr int ASTR  = 272;
    constexpr int BSTR  = 2320;
    constexpr int BBYT  = 74240;
    constexpr int V4    = 16;
    constexpr int APX   = 258;
    constexpr int ABYT  = APX * ASTR;      // 70176

    extern __shared__ __align__(16) char smem[];
    const int tid  = threadIdx.x;
    const int lane = tid & 31;
    const int wid  = tid >> 5;
    const int h0   = blockIdx.x << 1;      // 2 output rows
    const int b    = blockIdx.y;

    const uint32_t s0  = smem_u32(smem);
    const uint32_t sB  = s0;
    const uint32_t sA0 = s0 + BBYT;

    // group 0: B copy
    {
        for (int i = tid; i < BBYT / 16; i += 256)
            cp16(sB + i * 16, wb + i * 16, 16);
        cp_commit();
    }

    auto prefetch = [&](int s) {
        const int ir = h0 - 1 + s;
        const uint32_t abase = sA0 + (uint32_t)(s & 1) * ABYT;
        if ((unsigned)ir < 256u) {
            const size_t rowbase = ((size_t)b * HW + (size_t)ir * 256);
            for (int i = tid; i < APX * V4; i += 256) {
                int px = i / V4, v = i - px * V4;
                int w  = px - 1;
                int ok = ((unsigned)w < 256u);
                int wc = ok ? w : 0;
                int plane = v >> 2;
                const __half* src = a16 + (size_t)plane * PLANE + (rowbase + wc) * 32 + (v & 3) * 8;
                cp16(abase + (uint32_t)(px * ASTR + v * 16), src, ok ? 16 : 0);
            }
        }
        cp_commit();
    };
    prefetch(0);

    const int m0 = wid * 32;               // 32-px m range per warp
    const uint32_t aRowOff = (uint32_t)(lane & 15) * ASTR + ((lane & 16) ? 16u : 0u);
    const uint32_t bLM = (uint32_t)((lane & 7) + ((lane & 16) ? 8 : 0)) * BSTR
                       + (uint32_t)((lane >> 3) & 1) * 16;

    float acc[2][2][16];                   // [row][mtile][frag]
#pragma unroll
    for (int r = 0; r < 2; r++)
#pragma unroll
        for (int t = 0; t < 2; t++)
#pragma unroll
            for (int i = 0; i < 16; i++) acc[r][t][i] = 0.f;

    for (int s = 0; s < 4; s++) {
        const int ir = h0 - 1 + s;
        __syncthreads();
        if (s < 3) prefetch(s + 1);
        if (s < 3) cp_wait1(); else cp_wait0();
        __syncthreads();
        if ((unsigned)ir >= 256u) continue;

        const uint32_t sA = sA0 + (uint32_t)(s & 1) * ABYT;

#pragma unroll
        for (int dx = 0; dx < 3; dx++) {
#pragma unroll
            for (int kc = 0; kc < 8; kc++) {
                uint32_t a0f[4], a1f[4];
                const uint32_t ab = (uint32_t)(m0 + dx) * ASTR + kc * 32 + aRowOff;
                ldm4(a0f, sA + ab);
                ldm4(a1f, sA + ab + 16 * ASTR);
#pragma unroll
                for (int r = 0; r < 2; r++) {
                    const int dy = s - r;
                    if (dy < 0 || dy > 2) continue;
                    const uint32_t kb = (uint32_t)(dy * 384 + dx * 128 + kc * 16) * 2;
                    uint32_t bh[4], bh2[4];
                    ldm4(bh,  sB + bLM + kb);
                    ldm4(bh2, sB + bLM + kb + 16 * BSTR);
                    float* c0 = acc[r][0];
                    float* c1 = acc[r][1];
                    mma16816(c0 + 0,  a0f, bh[0],  bh[1]);
                    mma16816(c0 + 4,  a0f, bh[2],  bh[3]);
                    mma16816(c0 + 8,  a0f, bh2[0], bh2[1]);
                    mma16816(c0 + 12, a0f, bh2[2], bh2[3]);
                    mma16816(c1 + 0,  a1f, bh[0],  bh[1]);
                    mma16816(c1 + 4,  a1f, bh[2],  bh[3]);
                    mma16816(c1 + 8,  a1f, bh2[0], bh2[1]);
                    mma16816(c1 + 12, a1f, bh2[2], bh2[3]);
                }
            }
        }
    }

    // epilogue: 2 rows x 2 m-tiles
#pragma unroll
    for (int r = 0; r < 2; r++) {
        const int h = h0 + r;
#pragma unroll
        for (int t = 0; t < 2; t++) {
            const int prow = m0 + t * 16 + (lane >> 2);
            const float* a0 = acc[r][t];
            if (!FUSE) {
                __half* ob = (__half*)outv + ((size_t)b * HW + (size_t)h * 256) * 32;
#pragma unroll
                for (int nt = 0; nt < 4; nt++) {
                    int ch = nt * 8 + (lane & 3) * 2;
                    *(__half2*)(ob + (size_t)prow * 32 + ch) =
                        __floats2half2_rn(a0[nt * 4 + 0], a0[nt * 4 + 1]);
                    *(__half2*)(ob + (size_t)(prow + 8) * 32 + ch) =
                        __floats2half2_rn(a0[nt * 4 + 2], a0[nt * 4 + 3]);
                }
            } else {
                float s0v = 0.f, s1v = 0.f;
#pragma unroll
                for (int nt = 0; nt < 4; nt++) {
                    int ch = nt * 8 + (lane & 3) * 2;
                    float wa = __ldg(&wout[ch]), wb2 = __ldg(&wout[ch + 1]);
                    s0v += fmaxf(a0[nt * 4 + 0], 0.f) * wa + fmaxf(a0[nt * 4 + 1], 0.f) * wb2;
                    s1v += fmaxf(a0[nt * 4 + 2], 0.f) * wa + fmaxf(a0[nt * 4 + 3], 0.f) * wb2;
                }
                s0v += __shfl_xor_sync(0xffffffffu, s0v, 1);
                s0v += __shfl_xor_sync(0xffffffffu, s0v, 2);
                s1v += __shfl_xor_sync(0xffffffffu, s1v, 1);
                s1v += __shfl_xor_sync(0xffffffffu, s1v, 2);
                if ((lane & 3) == 0) {
                    float* outp = (float*)outv;
                    size_t ob = (size_t)b * HW + (size_t)h * 256;
                    outp[ob + prow]     = 1.0f / (1.0f + expf(-s0v));
                    outp[ob + prow + 8] = 1.0f / (1.0f + expf(-s1v));
                }
            }
        }
    }
}

// ---------------------------------------------------------------------------
// IRNN: all 4 directional scans in ONE kernel (blockIdx.y = direction).
// Thread owns a channel pair; output: direction-major plane [B][HW][32].
// ---------------------------------------------------------------------------
template<bool REV>
__device__ __forceinline__
void scan_h_body(const __half* __restrict__ in, __half* __restrict__ plane,
                 float wc0, float bc0, float wc1, float bc1, int c)
{
    int t = blockIdx.x * 256 + threadIdx.x;
    int w = (t >> 4) & 255, b = t >> 12;
    const __half2* ip = (const __half2*)(in + (size_t)b * HW * 32 + (size_t)w * 32 + c);
    __half2* op = (__half2*)(plane + ((size_t)b * HW + w) * 32 + c);

    __half2 v0 = REV ? ip[(size_t)255 * 4096] : ip[0];
    float h0 = __low2float(v0), h1 = __high2float(v0);
    op[(size_t)(REV ? 255 : 0) * 4096] = v0;
#pragma unroll 8
    for (int i = 1; i < 256; i++) {
        int y = REV ? (255 - i) : i;
        __half2 v = ip[(size_t)y * 4096];
        h0 = fmaxf(wc0 * h0 + (bc0 + __low2float(v)),  0.f);
        h1 = fmaxf(wc1 * h1 + (bc1 + __high2float(v)), 0.f);
        op[(size_t)y * 4096] = __floats2half2_rn(h0, h1);
    }
}

template<bool REV>
__device__ __forceinline__
void scan_w_body(const __half* __restrict__ in, __half* __restrict__ plane,
                 float wc0, float bc0, float wc1, float bc1, int c)
{
    int t = blockIdx.x * 256 + threadIdx.x;
    int h = (t >> 4) & 255, b = t >> 12;
    const __half2* ip = (const __half2*)(in + (size_t)b * HW * 32 + (size_t)h * 8192 + c);
    __half2* op = (__half2*)(plane + ((size_t)b * HW + (size_t)h * 256) * 32 + c);

    __half2 v0 = REV ? ip[255 * 16] : ip[0];
    float h0 = __low2float(v0), h1 = __high2float(v0);
    op[(size_t)(REV ? 255 : 0) * 16] = v0;
#pragma unroll 8
    for (int i = 1; i < 256; i++) {
        int w = REV ? (255 - i) : i;
        __half2 v = ip[w * 16];
        h0 = fmaxf(wc0 * h0 + (bc0 + __low2float(v)),  0.f);
        h1 = fmaxf(wc1 * h1 + (bc1 + __high2float(v)), 0.f);
        op[(size_t)w * 16] = __floats2half2_rn(h0, h1);
    }
}

__global__ __launch_bounds__(256)
void scan_all(const __half* __restrict__ in, __half* __restrict__ o16,
              const float* __restrict__ ws, const float* __restrict__ bs)
{
    const int d = blockIdx.y;
    const int c = (threadIdx.x & 15) * 2;
    const float wc0 = ws[d * 32 + c],     bc0 = bs[d * 32 + c];
    const float wc1 = ws[d * 32 + c + 1], bc1 = bs[d * 32 + c + 1];
    __half* plane = o16 + (size_t)d * PLANE;
    if      (d == 0) scan_h_body<true >(in, plane, wc0, bc0, wc1, bc1, c);   // up
    else if (d == 1) scan_w_body<false>(in, plane, wc0, bc0, wc1, bc1, c);   // right
    else if (d == 2) scan_h_body<false>(in, plane, wc0, bc0, wc1, bc1, c);   // down
    else             scan_w_body<true >(in, plane, wc0, bc0, wc1, bc1, c);   // left
}

// ---------------------------------------------------------------------------
extern "C" void kernel_launch(void* const* d_in, const int* in_sizes, int n_in,
                              void* d_out, int out_size)
{
    const float* x   = (const float*)d_in[0];
    const float* w1  = (const float*)d_in[1];
    const float* w2  = (const float*)d_in[2];
    const float* w3  = (const float*)d_in[3];
    const float* wo  = (const float*)d_in[4];
    const float* i1w = (const float*)d_in[5];
    const float* i1b = (const float*)d_in[6];
    const float* i2w = (const float*)d_in[7];
    const float* i2b = (const float*)d_in[8];
    float* outp = (float*)d_out;

    __half *gc, *gx, *ga;  char* gwb;
    cudaGetSymbolAddress((void**)&gc,  g_c16);
    cudaGetSymbolAddress((void**)&gx,  g_x16);
    cudaGetSymbolAddress((void**)&ga,  g_a16);
    cudaGetSymbolAddress((void**)&gwb, g_wb);

    cudaFuncSetAttribute(conv1_mma,        cudaFuncAttributeMaxDynamicSharedMemorySize, 39744);
    cudaFuncSetAttribute(conv_wide<false>, cudaFuncAttributeMaxDynamicSharedMemorySize, 214592);
    cudaFuncSetAttribute(conv_wide<true >, cudaFuncAttributeMaxDynamicSharedMemorySize, 214592);

    prep_all<<<dim3(145, 3), 256>>>(w1, w2, w3, gwb);

    transpose_x<<<dim3(2048, 8), 256>>>(x, gx);

    conv1_mma<<<dim3(2, 64, 8), 256, 39744>>>(gx, gwb + 0, gc);

    scan_all<<<dim3(128, 4), 256>>>(gc, ga, i1w, i1b);

    conv_wide<false><<<dim3(128, 8), 256, 214592>>>(ga, gwb + 18944, nullptr, gc);

    scan_all<<<dim3(128, 4), 256>>>(gc, ga, i2w, i2b);

    conv_wide<true><<<dim3(128, 8), 256, 214592>>>(ga, gwb + 93184, wo, outp);
}